// round 15
// baseline (speedup 1.0000x reference)
#include <cuda_runtime.h>
#include <cuda_fp16.h>
#include <cstdint>

#define NTOK 2048
#define NHEAD 8
#define EPSV 1e-6f
#define QKSCALE 0.17677669529663687f
#define PSCALE 1024.0f
#define INV_PSCALE (1.0f / 1024.0f)
#define NSPL 4
#define JR (NTOK / NSPL)      /* 512 per split */
#define TIA 32
#define TJA 32
#define NJT (JR / TJA)        /* 16 tiles */
#define RSTRB 528             /* smem row stride bytes (264 fp16) */
#define PLANEB 16896          /* 32*528 */
#define NX (NTOK * 256)       /* 524288 */

typedef unsigned long long ull;

__device__ float g_pn[NSPL * NTOK * 256];
__device__ float g_pd[NSPL * NTOK * NHEAD];
__device__ __align__(16) __half g_Qhl[2 * NX];
__device__ __align__(16) __half g_Khl[2 * NX];
__device__ __align__(16) __half g_Vhl[2 * NX];
__device__ __align__(16) __half g_Xhl[2 * NX];    /* x planes; reused as O planes */
__device__ __align__(16) __half g_Wall[4 * 2 * 256 * 256];

/* ---------------- warp-mma / async helpers ---------------- */
__device__ __forceinline__ uint32_t smem_u32(const void* p) {
    uint32_t a;
    asm("{ .reg .u64 t; cvta.to.shared.u64 t, %1; cvt.u32.u64 %0, t; }" : "=r"(a) : "l"(p));
    return a;
}
__device__ __forceinline__ void mma16816(float* d, const uint32_t* a, const uint32_t* b) {
    asm("mma.sync.aligned.m16n8k16.row.col.f32.f16.f16.f32 "
        "{%0,%1,%2,%3}, {%4,%5,%6,%7}, {%8,%9}, {%0,%1,%2,%3};"
        : "+f"(d[0]), "+f"(d[1]), "+f"(d[2]), "+f"(d[3])
        : "r"(a[0]), "r"(a[1]), "r"(a[2]), "r"(a[3]), "r"(b[0]), "r"(b[1]));
}
__device__ __forceinline__ void ldsm4(uint32_t* r, uint32_t a) {
    asm volatile("ldmatrix.sync.aligned.m8n8.x4.shared.b16 {%0,%1,%2,%3}, [%4];"
                 : "=r"(r[0]), "=r"(r[1]), "=r"(r[2]), "=r"(r[3]) : "r"(a));
}
__device__ __forceinline__ void ldsm2(uint32_t* r, uint32_t a) {
    asm volatile("ldmatrix.sync.aligned.m8n8.x2.shared.b16 {%0,%1}, [%2];"
                 : "=r"(r[0]), "=r"(r[1]) : "r"(a));
}
__device__ __forceinline__ void ldsm2t(uint32_t* r, uint32_t a) {
    asm volatile("ldmatrix.sync.aligned.m8n8.x2.trans.shared.b16 {%0,%1}, [%2];"
                 : "=r"(r[0]), "=r"(r[1]) : "r"(a));
}
__device__ __forceinline__ void cpa16(uint32_t d, const void* s) {
    asm volatile("cp.async.ca.shared.global [%0], [%1], 16;" :: "r"(d), "l"(s));
}
#define CP_COMMIT() asm volatile("cp.async.commit_group;" ::: "memory")
#define CP_WAIT0()  asm volatile("cp.async.wait_group 0;" ::: "memory")
#define CP_WAIT1()  asm volatile("cp.async.wait_group 1;" ::: "memory")
__device__ __forceinline__ void hiloh(float v, __half& h, __half& l) {
    h = __float2half_rn(v);
    l = __float2half_rn(v - __half2float(h));
}
__device__ __forceinline__ uint32_t packh(__half a, __half b) {
    return (uint32_t)*(unsigned short*)&a | ((uint32_t)*(unsigned short*)&b << 16);
}

/* =============== conv: x, Wq/Wk/Wv/Wo -> fp16 hi/lo planes =============== */
__global__ __launch_bounds__(256) void conv_inputs(const float* __restrict__ x,
                                                   const float* __restrict__ Wq,
                                                   const float* __restrict__ Wk,
                                                   const float* __restrict__ Wv,
                                                   const float* __restrict__ Wo)
{
    const int base = (blockIdx.x * 256 + threadIdx.x) * 4;
    float4 v;
    __half* dst;
    int stride;
    bool store_lo = true;
    if (base < NX) {
        v = *(const float4*)(x + base);
        dst = g_Xhl + base;
        stride = NX;
    } else {
        int wrem = base - NX;
        int wi = wrem >> 16, rem = wrem & 65535;
        const float* W = (wi == 0) ? Wq : (wi == 1) ? Wk : (wi == 2) ? Wv : Wo;
        v = *(const float4*)(W + rem);
        dst = g_Wall + wi * 131072 + rem;
        stride = 65536;
        store_lo = (wi == 3);   /* only Wo's lo plane is consumed (3-term out GEMM) */
    }
    __half h0, l0, h1, l1, h2, l2, h3, l3;
    hiloh(v.x, h0, l0); hiloh(v.y, h1, l1); hiloh(v.z, h2, l2); hiloh(v.w, h3, l3);
    *(ull*)dst = (ull)packh(h0, h1) | ((ull)packh(h2, h3) << 32);
    if (store_lo)
        *(ull*)(dst + stride) = (ull)packh(l0, l1) | ((ull)packh(l2, l3) << 32);
}

/* =============== hgemm body: planes/out = (A_planes @ W^T) =============== */
#define HPLANE 33792          /* 64*528 */
#define HSMEM  135168

template<bool TO_PLANES, bool THREE_TERM>
__device__ __forceinline__ void hgemm_body(const __half* __restrict__ Asrc,
                                           const __half* __restrict__ wsrc,
                                           __half* __restrict__ Pdst,
                                           float* __restrict__ Fdst,
                                           int i0, int nw)
{
    extern __shared__ __align__(16) char hsm[];
    const uint32_t sA = smem_u32(hsm);
    const uint32_t sB = sA + 2 * HPLANE;

    const int t = threadIdx.x, lane = t & 31, w = t >> 5;

    for (int c = t; c < 2048; c += 256) {
        int row = c >> 5, ch = c & 31;
        cpa16(sA + row * RSTRB + ch * 16,          Asrc + (size_t)(i0 + row) * 256 + ch * 8);
        cpa16(sA + HPLANE + row * RSTRB + ch * 16, Asrc + NX + (size_t)(i0 + row) * 256 + ch * 8);
        cpa16(sB + row * RSTRB + ch * 16,          wsrc + (size_t)row * 256 + ch * 8);
        if (THREE_TERM)
            cpa16(sB + HPLANE + row * RSTRB + ch * 16, wsrc + 65536 + (size_t)row * 256 + ch * 8);
    }
    CP_COMMIT(); CP_WAIT0();
    __syncthreads();

    const int mrow = (w >> 1) * 16;
    const int ncol = (w & 1) * 32;

    float acc[4][4];
#pragma unroll
    for (int n8 = 0; n8 < 4; n8++)
#pragma unroll
        for (int c = 0; c < 4; c++) acc[n8][c] = 0.f;

#pragma unroll 4
    for (int ks = 0; ks < 16; ks++) {
        uint32_t ah[4], al[4];
        {
            int row = mrow + (lane & 15);
            int col = ks * 16 + (lane >> 4) * 8;
            uint32_t ad = sA + row * RSTRB + col * 2;
            ldsm4(ah, ad);
            ldsm4(al, ad + HPLANE);
        }
#pragma unroll
        for (int n8 = 0; n8 < 4; n8++) {
            int row = ncol + n8 * 8 + (lane & 7);
            int col = ks * 16 + ((lane >> 3) & 1) * 8;
            uint32_t bd = sB + row * RSTRB + col * 2;
            uint32_t bh[2];
            ldsm2(bh, bd);
            mma16816(acc[n8], ah, bh);
            mma16816(acc[n8], al, bh);
            if (THREE_TERM) {
                uint32_t bl[2];
                ldsm2(bl, bd + HPLANE);
                mma16816(acc[n8], ah, bl);
            }
        }
    }

#pragma unroll
    for (int n8 = 0; n8 < 4; n8++) {
        int cg = nw + ncol + n8 * 8 + 2 * (lane & 3);
        int rg = i0 + mrow + (lane >> 2);
        if (TO_PLANES) {
            *(uint32_t*)(Pdst + (size_t)rg * 256 + cg) =
                packh(__float2half_rn(acc[n8][0]), __float2half_rn(acc[n8][1]));
            *(uint32_t*)(Pdst + (size_t)(rg + 8) * 256 + cg) =
                packh(__float2half_rn(acc[n8][2]), __float2half_rn(acc[n8][3]));
        } else {
            *(float2*)(Fdst + (size_t)rg * 256 + cg) = make_float2(acc[n8][0], acc[n8][1]);
            *(float2*)(Fdst + (size_t)(rg + 8) * 256 + cg) = make_float2(acc[n8][2], acc[n8][3]);
        }
    }
}

__global__ __launch_bounds__(256) void hgemm_qkv()
{
    const int bn = blockIdx.x;            /* 0..11 */
    const int widx = bn >> 2;
    const int nw = (bn & 3) * 64;
    __half* P = (widx == 0) ? g_Qhl : (widx == 1) ? g_Khl : g_Vhl;
    hgemm_body<true, false>(g_Xhl, g_Wall + widx * 131072 + nw * 256, P, nullptr,
                            blockIdx.y * 64, nw);
}

__global__ __launch_bounds__(256) void hgemm_out(float* __restrict__ out)
{
    const int nw = blockIdx.x * 64;
    hgemm_body<false, true>(g_Xhl, g_Wall + 3 * 131072 + nw * 256, nullptr, out,
                            blockIdx.y * 64, nw);
}

/* =============== combine_o: fold split partials -> O fp16 planes (reuse g_Xhl) =============== */
__global__ __launch_bounds__(256) void combine_o()
{
    const int idx4 = blockIdx.x * 256 + threadIdx.x;   /* 0..131071 */
    const int row = idx4 >> 6;
    const int c0 = (idx4 & 63) * 4;
    float4 n = *(const float4*)(g_pn + (size_t)row * 256 + c0);
    float den = g_pd[row * NHEAD + (c0 >> 5)];
#pragma unroll
    for (int s = 1; s < NSPL; s++) {
        float4 n2 = *(const float4*)(g_pn + (size_t)s * NTOK * 256 + (size_t)row * 256 + c0);
        n.x += n2.x; n.y += n2.y; n.z += n2.z; n.w += n2.w;
        den += g_pd[s * NTOK * NHEAD + row * NHEAD + (c0 >> 5)];
    }
    float inv = 1.0f / den;
    __half h0, l0, h1, l1, h2, l2, h3, l3;
    hiloh(n.x * inv, h0, l0); hiloh(n.y * inv, h1, l1);
    hiloh(n.z * inv, h2, l2); hiloh(n.w * inv, h3, l3);
    __half* d = g_Xhl + (size_t)row * 256 + c0;
    *(ull*)d        = (ull)packh(h0, h1) | ((ull)packh(h2, h3) << 32);
    *(ull*)(d + NX) = (ull)packh(l0, l1) | ((ull)packh(l2, l3) << 32);
}

/* =============== warp-mma attention: double-buffered Kh/Vh, 2 CTAs/SM =============== */
#define BUFB (2 * PLANEB)               /* 33792: one buffer = K plane + V plane */
#define OFF_W   (2 * BUFB)              /* 67584: float Ws[8][32][33] = 33792 */
#define OFF_PIT (OFF_W + 33792)         /* 101376: 4096 */
#define SMEM_BYTES (OFF_PIT + 4096)     /* 105472 */

__global__ __launch_bounds__(256, 2) void attn_mma(
    const float* __restrict__ pi, const float* __restrict__ tau,
    const float* __restrict__ adjs)
{
    extern __shared__ __align__(16) char smraw[];
    const uint32_t sb = smem_u32(smraw);
    float* Ws   = (float*)(smraw + OFF_W);
    float* pits = (float*)(smraw + OFF_PIT);

    const int t = threadIdx.x, lane = t & 31, h = t >> 5;
    const int i0 = blockIdx.x * TIA;
    const int sy = blockIdx.y;
    const int jbase = sy * JR;
    const size_t NN = (size_t)NTOK * NTOK;

    for (int idx = t; idx < TIA * 32; idx += 256) {
        int hm = idx & 31;
        pits[idx] = tau[hm >> 2] * pi[(size_t)(i0 + (idx >> 5)) * 32 + hm];
    }

    /* ---- stage Q hi plane into K buf0, pull A-fragments ---- */
#pragma unroll
    for (int k = 0; k < 4; k++) {
        int idx = t + k * 256;              /* 1024 chunks of 16B */
        int row = idx >> 5, c16 = idx & 31;
        const __half* s = g_Qhl + (size_t)(i0 + row) * 256 + c16 * 8;
        ull v = *(const ull*)s, v2 = *(const ull*)(s + 4);
        char* d = smraw + row * RSTRB + c16 * 16;
        *(ull*)d = v; *(ull*)(d + 8) = v2;
    }
    __syncthreads();
    uint32_t qh[2][2][4];
#pragma unroll
    for (int it = 0; it < 2; it++)
#pragma unroll
        for (int ks = 0; ks < 2; ks++) {
            int row = it * 16 + (lane & 15);
            int col = 32 * h + ks * 16 + (lane >> 4) * 8;
            ldsm4(qh[it][ks], sb + row * RSTRB + col * 2);
        }
    __syncthreads();   /* all Q fragment reads done before buf0 is overwritten */

    /* per-thread cp.async mapping: 8 chunks (Kh, Vh planes) within one buffer */
    uint32_t cdst[8];
    const __half* csrc_base[8];
    int crow[8];
#pragma unroll
    for (int k = 0; k < 8; k++) {
        int idx = t + k * 256;              /* 2048: plane(K/V) x row x c16 */
        int plane = idx >> 10, r3 = idx & 1023, row = r3 >> 5, c16 = r3 & 31;
        cdst[k] = sb + plane * PLANEB + row * RSTRB + c16 * 16;
        csrc_base[k] = (plane ? g_Vhl : g_Khl) + c16 * 8;
        crow[k] = row;
    }

    /* prefetch tile 0 into buf 0 */
#pragma unroll
    for (int k = 0; k < 8; k++)
        cpa16(cdst[k], csrc_base[k] + (size_t)(jbase + crow[k]) * 256);
    CP_COMMIT();

    float O[2][4][4];
#pragma unroll
    for (int it = 0; it < 2; it++)
#pragma unroll
        for (int n8 = 0; n8 < 4; n8++)
#pragma unroll
            for (int c = 0; c < 4; c++) O[it][n8][c] = 0.f;
    float rsum[4] = {0.f, 0.f, 0.f, 0.f};

    const int wi = t >> 3;
    const int wj4 = (t & 7) * 4;

    for (int jt = 0; jt < NJT; jt++) {
        const int cur = jt & 1;
        const int j0 = jbase + jt * TJA;
        __syncthreads();   /* Ws + buf[cur^1] reads of tile jt-1 done */

        /* prefetch NEXT tile into the other buffer */
        if (jt + 1 < NJT) {
            const int jn = j0 + TJA;
            const uint32_t boff = (cur ^ 1) * BUFB;
#pragma unroll
            for (int k = 0; k < 8; k++)
                cpa16(cdst[k] + boff, csrc_base[k] + (size_t)(jn + crow[k]) * 256);
        }
        CP_COMMIT();

        /* adjs loads + graph weights (overlap the in-flight loads) */
        const float* ab = adjs + (size_t)(i0 + wi) * NTOK + j0 + wj4;
        float4 a0 = *(const float4*)(ab);
        float4 a1 = *(const float4*)(ab + NN);
        float4 a2 = *(const float4*)(ab + 2 * NN);
        float4 a3 = *(const float4*)(ab + 3 * NN);
        {
            const float* pp = pits + wi * 32;
#pragma unroll
            for (int hh = 0; hh < NHEAD; hh++) {
                float p0 = pp[hh * 4 + 0], p1 = pp[hh * 4 + 1], p2 = pp[hh * 4 + 2], p3 = pp[hh * 4 + 3];
                float* wd = Ws + (hh * 32 + wi) * 33 + wj4;
                wd[0] = fmaf(p3, a3.x, fmaf(p2, a2.x, fmaf(p1, a1.x, fmaf(p0, a0.x, EPSV))));
                wd[1] = fmaf(p3, a3.y, fmaf(p2, a2.y, fmaf(p1, a1.y, fmaf(p0, a0.y, EPSV))));
                wd[2] = fmaf(p3, a3.z, fmaf(p2, a2.z, fmaf(p1, a1.z, fmaf(p0, a0.z, EPSV))));
                wd[3] = fmaf(p3, a3.w, fmaf(p2, a2.w, fmaf(p1, a1.w, fmaf(p0, a0.w, EPSV))));
            }
        }
        CP_WAIT1();        /* this tile's K/V landed; next tile still in flight */
        __syncthreads();

        /* ---- QK^T: S = Qh*Kh ---- */
        float S[2][4][4];
#pragma unroll
        for (int it = 0; it < 2; it++)
#pragma unroll
            for (int j8 = 0; j8 < 4; j8++)
#pragma unroll
                for (int c = 0; c < 4; c++) S[it][j8][c] = 0.f;
        const uint32_t kbase = sb + cur * BUFB;
#pragma unroll
        for (int j8 = 0; j8 < 4; j8++)
#pragma unroll
            for (int ks = 0; ks < 2; ks++) {
                int krow = j8 * 8 + (lane & 7);
                int kcol = 32 * h + ks * 16 + ((lane >> 3) & 1) * 8;
                uint32_t bh[2];
                ldsm2(bh, kbase + krow * RSTRB + kcol * 2);
#pragma unroll
                for (int it = 0; it < 2; it++)
                    mma16816(S[it][j8], qh[it][ks], bh);
            }

        /* ---- p = w * exp(s*scale); single fp16 P (scaled) ---- */
        uint32_t ph[2][2][4];
#pragma unroll
        for (int it = 0; it < 2; it++)
#pragma unroll
            for (int j8 = 0; j8 < 4; j8++) {
                int r0 = it * 16 + (lane >> 2);
                int c0 = j8 * 8 + 2 * (lane & 3);
                const float* wr0 = Ws + (h * 32 + r0) * 33 + c0;
                const float* wr1 = Ws + (h * 32 + r0 + 8) * 33 + c0;
                float p0 = wr0[0] * __expf(S[it][j8][0] * QKSCALE);
                float p1 = wr0[1] * __expf(S[it][j8][1] * QKSCALE);
                float p2 = wr1[0] * __expf(S[it][j8][2] * QKSCALE);
                float p3 = wr1[1] * __expf(S[it][j8][3] * QKSCALE);
                rsum[it * 2 + 0] += p0 + p1;
                rsum[it * 2 + 1] += p2 + p3;
                __half f0 = __float2half_rn(p0 * PSCALE);
                __half f1 = __float2half_rn(p1 * PSCALE);
                __half f2 = __float2half_rn(p2 * PSCALE);
                __half f3 = __float2half_rn(p3 * PSCALE);
                int kc = j8 >> 1, sl = (j8 & 1) * 2;
                ph[it][kc][sl + 0] = packh(f0, f1);
                ph[it][kc][sl + 1] = packh(f2, f3);
            }

        /* ---- O += P @ Vh ---- */
        const uint32_t vbase = sb + cur * BUFB + PLANEB;
#pragma unroll
        for (int n8 = 0; n8 < 4; n8++)
#pragma unroll
            for (int kc = 0; kc < 2; kc++) {
                int vrow = kc * 16 + (lane & 15);
                int vcol = 32 * h + n8 * 8;
                uint32_t vh[2];
                ldsm2t(vh, vbase + vrow * RSTRB + vcol * 2);
#pragma unroll
                for (int it = 0; it < 2; it++)
                    mma16816(O[it][n8], ph[it][kc], vh);
            }
    }

    /* ---- epilogue ---- */
#pragma unroll
    for (int v = 0; v < 4; v++) {
        float x = rsum[v];
        x += __shfl_xor_sync(0xffffffffu, x, 1);
        x += __shfl_xor_sync(0xffffffffu, x, 2);
        rsum[v] = x;
    }
    if ((lane & 3) == 0) {
#pragma unroll
        for (int it = 0; it < 2; it++)
#pragma unroll
            for (int half = 0; half < 2; half++) {
                int row = it * 16 + (lane >> 2) + half * 8;
                g_pd[(size_t)sy * NTOK * NHEAD + (size_t)(i0 + row) * NHEAD + h] = rsum[it * 2 + half];
            }
    }
    float* pn = g_pn + (size_t)sy * NTOK * 256;
#pragma unroll
    for (int it = 0; it < 2; it++)
#pragma unroll
        for (int n8 = 0; n8 < 4; n8++) {
            int r0 = i0 + it * 16 + (lane >> 2);
            int c = 32 * h + n8 * 8 + 2 * (lane & 3);
            *(float2*)(pn + (size_t)r0 * 256 + c) =
                make_float2(O[it][n8][0] * INV_PSCALE, O[it][n8][1] * INV_PSCALE);
            *(float2*)(pn + (size_t)(r0 + 8) * 256 + c) =
                make_float2(O[it][n8][2] * INV_PSCALE, O[it][n8][3] * INV_PSCALE);
        }
}

/* ================================================================= */
extern "C" void kernel_launch(void* const* d_in, const int* in_sizes, int n_in,
                              void* d_out, int out_size)
{
    const float* x    = (const float*)d_in[0];
    const float* pi   = (const float*)d_in[1];
    const float* tau  = (const float*)d_in[2];
    const float* adjs = (const float*)d_in[3];
    const float* Wq   = (const float*)d_in[4];
    const float* Wk   = (const float*)d_in[5];
    const float* Wv   = (const float*)d_in[6];
    const float* Wo   = (const float*)d_in[7];
    float* out = (float*)d_out;

    cudaFuncSetAttribute(attn_mma, cudaFuncAttributeMaxDynamicSharedMemorySize, SMEM_BYTES);
    cudaFuncSetAttribute(hgemm_qkv, cudaFuncAttributeMaxDynamicSharedMemorySize, HSMEM);
    cudaFuncSetAttribute(hgemm_out, cudaFuncAttributeMaxDynamicSharedMemorySize, HSMEM);

    conv_inputs<<<768, 256>>>(x, Wq, Wk, Wv, Wo);
    hgemm_qkv<<<dim3(12, 32), 256, HSMEM>>>();
    attn_mma<<<dim3(NTOK / TIA, NSPL), 256, SMEM_BYTES>>>(pi, tau, adjs);
    combine_o<<<512, 256>>>();
    hgemm_out<<<dim3(4, 32), 256, HSMEM>>>(out);
}

// round 16
// speedup vs baseline: 1.0856x; 1.0856x over previous
#include <cuda_runtime.h>
#include <cuda_fp16.h>
#include <cstdint>

#define NTOK 2048
#define NHEAD 8
#define EPSV 1e-6f
#define QKSCALE 0.17677669529663687f
#define PSCALE 1024.0f
#define INV_PSCALE (1.0f / 1024.0f)
#define NSPL 4
#define JR (NTOK / NSPL)      /* 512 per split */
#define TIA 32
#define TJA 32
#define NJT (JR / TJA)        /* 16 tiles */
#define RSTRB 528             /* smem row stride bytes (264 fp16) */
#define PLANEB 16896          /* 32*528 */
#define NX (NTOK * 256)       /* 524288 */
#define NTILE (NTOK / TIA)    /* 64 i-tiles */

typedef unsigned long long ull;

__device__ float g_pn[NSPL * NTOK * 256];
__device__ float g_pd[NSPL * NTOK * NHEAD];
__device__ int   g_tick[NTILE];
__device__ __align__(16) __half g_Qhl[2 * NX];
__device__ __align__(16) __half g_Khl[2 * NX];
__device__ __align__(16) __half g_Vhl[2 * NX];
__device__ __align__(16) __half g_Xhl[2 * NX];    /* x planes; reused as O planes */
__device__ __align__(16) __half g_Wall[4 * 2 * 256 * 256];

/* ---------------- warp-mma / async helpers ---------------- */
__device__ __forceinline__ uint32_t smem_u32(const void* p) {
    uint32_t a;
    asm("{ .reg .u64 t; cvta.to.shared.u64 t, %1; cvt.u32.u64 %0, t; }" : "=r"(a) : "l"(p));
    return a;
}
__device__ __forceinline__ void mma16816(float* d, const uint32_t* a, const uint32_t* b) {
    asm("mma.sync.aligned.m16n8k16.row.col.f32.f16.f16.f32 "
        "{%0,%1,%2,%3}, {%4,%5,%6,%7}, {%8,%9}, {%0,%1,%2,%3};"
        : "+f"(d[0]), "+f"(d[1]), "+f"(d[2]), "+f"(d[3])
        : "r"(a[0]), "r"(a[1]), "r"(a[2]), "r"(a[3]), "r"(b[0]), "r"(b[1]));
}
__device__ __forceinline__ void ldsm4(uint32_t* r, uint32_t a) {
    asm volatile("ldmatrix.sync.aligned.m8n8.x4.shared.b16 {%0,%1,%2,%3}, [%4];"
                 : "=r"(r[0]), "=r"(r[1]), "=r"(r[2]), "=r"(r[3]) : "r"(a));
}
__device__ __forceinline__ void ldsm2(uint32_t* r, uint32_t a) {
    asm volatile("ldmatrix.sync.aligned.m8n8.x2.shared.b16 {%0,%1}, [%2];"
                 : "=r"(r[0]), "=r"(r[1]) : "r"(a));
}
__device__ __forceinline__ void ldsm2t(uint32_t* r, uint32_t a) {
    asm volatile("ldmatrix.sync.aligned.m8n8.x2.trans.shared.b16 {%0,%1}, [%2];"
                 : "=r"(r[0]), "=r"(r[1]) : "r"(a));
}
__device__ __forceinline__ void cpa16(uint32_t d, const void* s) {
    asm volatile("cp.async.ca.shared.global [%0], [%1], 16;" :: "r"(d), "l"(s));
}
#define CP_COMMIT() asm volatile("cp.async.commit_group;" ::: "memory")
#define CP_WAIT0()  asm volatile("cp.async.wait_group 0;" ::: "memory")
__device__ __forceinline__ void hiloh(float v, __half& h, __half& l) {
    h = __float2half_rn(v);
    l = __float2half_rn(v - __half2float(h));
}
__device__ __forceinline__ uint32_t packh(__half a, __half b) {
    return (uint32_t)*(unsigned short*)&a | ((uint32_t)*(unsigned short*)&b << 16);
}

/* =============== conv: x, Wq/Wk/Wv/Wo -> fp16 hi/lo planes; reset tickets =============== */
__global__ __launch_bounds__(256) void conv_inputs(const float* __restrict__ x,
                                                   const float* __restrict__ Wq,
                                                   const float* __restrict__ Wk,
                                                   const float* __restrict__ Wv,
                                                   const float* __restrict__ Wo)
{
    if (blockIdx.x == 0 && threadIdx.x < NTILE)
        g_tick[threadIdx.x] = 0;

    const int base = (blockIdx.x * 256 + threadIdx.x) * 4;
    float4 v;
    __half* dst;
    int stride;
    bool store_lo = true;
    if (base < NX) {
        v = *(const float4*)(x + base);
        dst = g_Xhl + base;
        stride = NX;
    } else {
        int wrem = base - NX;
        int wi = wrem >> 16, rem = wrem & 65535;
        const float* W = (wi == 0) ? Wq : (wi == 1) ? Wk : (wi == 2) ? Wv : Wo;
        v = *(const float4*)(W + rem);
        dst = g_Wall + wi * 131072 + rem;
        stride = 65536;
        store_lo = (wi == 3);   /* only Wo's lo plane is consumed (3-term out GEMM) */
    }
    __half h0, l0, h1, l1, h2, l2, h3, l3;
    hiloh(v.x, h0, l0); hiloh(v.y, h1, l1); hiloh(v.z, h2, l2); hiloh(v.w, h3, l3);
    *(ull*)dst = (ull)packh(h0, h1) | ((ull)packh(h2, h3) << 32);
    if (store_lo)
        *(ull*)(dst + stride) = (ull)packh(l0, l1) | ((ull)packh(l2, l3) << 32);
}

/* =============== hgemm body: planes/out = (A_planes @ W^T) =============== */
#define HPLANE 33792          /* 64*528 */
#define HSMEM  135168

template<bool TO_PLANES, bool THREE_TERM>
__device__ __forceinline__ void hgemm_body(const __half* __restrict__ Asrc,
                                           const __half* __restrict__ wsrc,
                                           __half* __restrict__ Pdst,
                                           float* __restrict__ Fdst,
                                           int i0, int nw)
{
    extern __shared__ __align__(16) char hsm[];
    const uint32_t sA = smem_u32(hsm);
    const uint32_t sB = sA + 2 * HPLANE;

    const int t = threadIdx.x, lane = t & 31, w = t >> 5;

    for (int c = t; c < 2048; c += 256) {
        int row = c >> 5, ch = c & 31;
        cpa16(sA + row * RSTRB + ch * 16,          Asrc + (size_t)(i0 + row) * 256 + ch * 8);
        cpa16(sA + HPLANE + row * RSTRB + ch * 16, Asrc + NX + (size_t)(i0 + row) * 256 + ch * 8);
        cpa16(sB + row * RSTRB + ch * 16,          wsrc + (size_t)row * 256 + ch * 8);
        if (THREE_TERM)
            cpa16(sB + HPLANE + row * RSTRB + ch * 16, wsrc + 65536 + (size_t)row * 256 + ch * 8);
    }
    CP_COMMIT(); CP_WAIT0();
    __syncthreads();

    const int mrow = (w >> 1) * 16;
    const int ncol = (w & 1) * 32;

    float acc[4][4];
#pragma unroll
    for (int n8 = 0; n8 < 4; n8++)
#pragma unroll
        for (int c = 0; c < 4; c++) acc[n8][c] = 0.f;

#pragma unroll 4
    for (int ks = 0; ks < 16; ks++) {
        uint32_t ah[4], al[4];
        {
            int row = mrow + (lane & 15);
            int col = ks * 16 + (lane >> 4) * 8;
            uint32_t ad = sA + row * RSTRB + col * 2;
            ldsm4(ah, ad);
            ldsm4(al, ad + HPLANE);
        }
#pragma unroll
        for (int n8 = 0; n8 < 4; n8++) {
            int row = ncol + n8 * 8 + (lane & 7);
            int col = ks * 16 + ((lane >> 3) & 1) * 8;
            uint32_t bd = sB + row * RSTRB + col * 2;
            uint32_t bh[2];
            ldsm2(bh, bd);
            mma16816(acc[n8], ah, bh);
            mma16816(acc[n8], al, bh);
            if (THREE_TERM) {
                uint32_t bl[2];
                ldsm2(bl, bd + HPLANE);
                mma16816(acc[n8], ah, bl);
            }
        }
    }

#pragma unroll
    for (int n8 = 0; n8 < 4; n8++) {
        int cg = nw + ncol + n8 * 8 + 2 * (lane & 3);
        int rg = i0 + mrow + (lane >> 2);
        if (TO_PLANES) {
            *(uint32_t*)(Pdst + (size_t)rg * 256 + cg) =
                packh(__float2half_rn(acc[n8][0]), __float2half_rn(acc[n8][1]));
            *(uint32_t*)(Pdst + (size_t)(rg + 8) * 256 + cg) =
                packh(__float2half_rn(acc[n8][2]), __float2half_rn(acc[n8][3]));
        } else {
            *(float2*)(Fdst + (size_t)rg * 256 + cg) = make_float2(acc[n8][0], acc[n8][1]);
            *(float2*)(Fdst + (size_t)(rg + 8) * 256 + cg) = make_float2(acc[n8][2], acc[n8][3]);
        }
    }
}

__global__ __launch_bounds__(256) void hgemm_qkv()
{
    const int bn = blockIdx.x;            /* 0..11 */
    const int widx = bn >> 2;
    const int nw = (bn & 3) * 64;
    __half* P = (widx == 0) ? g_Qhl : (widx == 1) ? g_Khl : g_Vhl;
    hgemm_body<true, false>(g_Xhl, g_Wall + widx * 131072 + nw * 256, P, nullptr,
                            blockIdx.y * 64, nw);
}

__global__ __launch_bounds__(256) void hgemm_out(float* __restrict__ out)
{
    const int nw = blockIdx.x * 64;
    hgemm_body<false, true>(g_Xhl, g_Wall + 3 * 131072 + nw * 256, nullptr, out,
                            blockIdx.y * 64, nw);
}

/* =============== warp-mma attention (R13 structure) + fused last-CTA combine =============== */
#define OFF_K   0                       /* 1 plane: 16896 */
#define OFF_V   PLANEB                  /* 1 plane: 16896 */
#define OFF_W   (2 * PLANEB)            /* float Ws[8][32][33] = 33792 */
#define OFF_PIT (OFF_W + 33792)         /* 4096 */
#define SMEM_BYTES (OFF_PIT + 4096)     /* 71680 */

__global__ __launch_bounds__(256, 2) void attn_mma(
    const float* __restrict__ pi, const float* __restrict__ tau,
    const float* __restrict__ adjs)
{
    extern __shared__ __align__(16) char smraw[];
    const uint32_t sb = smem_u32(smraw);
    float* Ws   = (float*)(smraw + OFF_W);
    float* pits = (float*)(smraw + OFF_PIT);
    __shared__ int s_tick;

    const int t = threadIdx.x, lane = t & 31, h = t >> 5;
    const int i0 = blockIdx.x * TIA;
    const int sy = blockIdx.y;
    const int jbase = sy * JR;
    const size_t NN = (size_t)NTOK * NTOK;

    for (int idx = t; idx < TIA * 32; idx += 256) {
        int hm = idx & 31;
        pits[idx] = tau[hm >> 2] * pi[(size_t)(i0 + (idx >> 5)) * 32 + hm];
    }

    /* ---- stage Q hi plane into K buffer, pull A-fragments ---- */
#pragma unroll
    for (int k = 0; k < 4; k++) {
        int idx = t + k * 256;              /* 1024 chunks of 16B */
        int row = idx >> 5, c16 = idx & 31;
        const __half* s = g_Qhl + (size_t)(i0 + row) * 256 + c16 * 8;
        ull v = *(const ull*)s, v2 = *(const ull*)(s + 4);
        char* d = smraw + OFF_K + row * RSTRB + c16 * 16;
        *(ull*)d = v; *(ull*)(d + 8) = v2;
    }
    __syncthreads();
    uint32_t qh[2][2][4];
#pragma unroll
    for (int it = 0; it < 2; it++)
#pragma unroll
        for (int ks = 0; ks < 2; ks++) {
            int row = it * 16 + (lane & 15);
            int col = 32 * h + ks * 16 + (lane >> 4) * 8;
            ldsm4(qh[it][ks], sb + OFF_K + row * RSTRB + col * 2);
        }

    /* per-thread cp.async mapping: 8 chunks (Kh, Vh planes) */
    uint32_t cdst[8];
    const __half* csrc_base[8];
    int crow[8];
#pragma unroll
    for (int k = 0; k < 8; k++) {
        int idx = t + k * 256;              /* 2048: plane(K/V) x row x c16 */
        int plane = idx >> 10, r3 = idx & 1023, row = r3 >> 5, c16 = r3 & 31;
        cdst[k] = sb + (plane ? OFF_V : OFF_K) + row * RSTRB + c16 * 16;
        csrc_base[k] = (plane ? g_Vhl : g_Khl) + c16 * 8;
        crow[k] = row;
    }

    float O[2][4][4];
#pragma unroll
    for (int it = 0; it < 2; it++)
#pragma unroll
        for (int n8 = 0; n8 < 4; n8++)
#pragma unroll
            for (int c = 0; c < 4; c++) O[it][n8][c] = 0.f;
    float rsum[4] = {0.f, 0.f, 0.f, 0.f};

    const int wi = t >> 3;
    const int wj4 = (t & 7) * 4;

    for (int jt = 0; jt < NJT; jt++) {
        const int j0 = jbase + jt * TJA;
        __syncthreads();   /* reads of previous tile (and Q fragments) done */

        /* issue this tile's K/V loads */
#pragma unroll
        for (int k = 0; k < 8; k++)
            cpa16(cdst[k], csrc_base[k] + (size_t)(j0 + crow[k]) * 256);
        CP_COMMIT();

        /* adjs loads + graph weights (overlap the cp.async) */
        const float* ab = adjs + (size_t)(i0 + wi) * NTOK + j0 + wj4;
        float4 a0 = *(const float4*)(ab);
        float4 a1 = *(const float4*)(ab + NN);
        float4 a2 = *(const float4*)(ab + 2 * NN);
        float4 a3 = *(const float4*)(ab + 3 * NN);
        {
            const float* pp = pits + wi * 32;
#pragma unroll
            for (int hh = 0; hh < NHEAD; hh++) {
                float p0 = pp[hh * 4 + 0], p1 = pp[hh * 4 + 1], p2 = pp[hh * 4 + 2], p3 = pp[hh * 4 + 3];
                float* wd = Ws + (hh * 32 + wi) * 33 + wj4;
                wd[0] = fmaf(p3, a3.x, fmaf(p2, a2.x, fmaf(p1, a1.x, fmaf(p0, a0.x, EPSV))));
                wd[1] = fmaf(p3, a3.y, fmaf(p2, a2.y, fmaf(p1, a1.y, fmaf(p0, a0.y, EPSV))));
                wd[2] = fmaf(p3, a3.z, fmaf(p2, a2.z, fmaf(p1, a1.z, fmaf(p0, a0.z, EPSV))));
                wd[3] = fmaf(p3, a3.w, fmaf(p2, a2.w, fmaf(p1, a1.w, fmaf(p0, a0.w, EPSV))));
            }
        }
        CP_WAIT0();
        __syncthreads();

        /* ---- QK^T: S = Qh*Kh ---- */
        float S[2][4][4];
#pragma unroll
        for (int it = 0; it < 2; it++)
#pragma unroll
            for (int j8 = 0; j8 < 4; j8++)
#pragma unroll
                for (int c = 0; c < 4; c++) S[it][j8][c] = 0.f;
#pragma unroll
        for (int j8 = 0; j8 < 4; j8++)
#pragma unroll
            for (int ks = 0; ks < 2; ks++) {
                int krow = j8 * 8 + (lane & 7);
                int kcol = 32 * h + ks * 16 + ((lane >> 3) & 1) * 8;
                uint32_t bh[2];
                ldsm2(bh, sb + OFF_K + krow * RSTRB + kcol * 2);
#pragma unroll
                for (int it = 0; it < 2; it++)
                    mma16816(S[it][j8], qh[it][ks], bh);
            }

        /* ---- p = w * exp(s*scale); single fp16 P (scaled) ---- */
        uint32_t ph[2][2][4];
#pragma unroll
        for (int it = 0; it < 2; it++)
#pragma unroll
            for (int j8 = 0; j8 < 4; j8++) {
                int r0 = it * 16 + (lane >> 2);
                int c0 = j8 * 8 + 2 * (lane & 3);
                const float* wr0 = Ws + (h * 32 + r0) * 33 + c0;
                const float* wr1 = Ws + (h * 32 + r0 + 8) * 33 + c0;
                float p0 = wr0[0] * __expf(S[it][j8][0] * QKSCALE);
                float p1 = wr0[1] * __expf(S[it][j8][1] * QKSCALE);
                float p2 = wr1[0] * __expf(S[it][j8][2] * QKSCALE);
                float p3 = wr1[1] * __expf(S[it][j8][3] * QKSCALE);
                rsum[it * 2 + 0] += p0 + p1;
                rsum[it * 2 + 1] += p2 + p3;
                __half f0 = __float2half_rn(p0 * PSCALE);
                __half f1 = __float2half_rn(p1 * PSCALE);
                __half f2 = __float2half_rn(p2 * PSCALE);
                __half f3 = __float2half_rn(p3 * PSCALE);
                int kc = j8 >> 1, sl = (j8 & 1) * 2;
                ph[it][kc][sl + 0] = packh(f0, f1);
                ph[it][kc][sl + 1] = packh(f2, f3);
            }

        /* ---- O += P @ Vh ---- */
#pragma unroll
        for (int n8 = 0; n8 < 4; n8++)
#pragma unroll
            for (int kc = 0; kc < 2; kc++) {
                int vrow = kc * 16 + (lane & 15);
                int vcol = 32 * h + n8 * 8;
                uint32_t vh[2];
                ldsm2t(vh, sb + OFF_V + vrow * RSTRB + vcol * 2);
#pragma unroll
                for (int it = 0; it < 2; it++)
                    mma16816(O[it][n8], ph[it][kc], vh);
            }
    }

    /* ---- epilogue: write split partials ---- */
#pragma unroll
    for (int v = 0; v < 4; v++) {
        float x = rsum[v];
        x += __shfl_xor_sync(0xffffffffu, x, 1);
        x += __shfl_xor_sync(0xffffffffu, x, 2);
        rsum[v] = x;
    }
    if ((lane & 3) == 0) {
#pragma unroll
        for (int it = 0; it < 2; it++)
#pragma unroll
            for (int half = 0; half < 2; half++) {
                int row = it * 16 + (lane >> 2) + half * 8;
                g_pd[(size_t)sy * NTOK * NHEAD + (size_t)(i0 + row) * NHEAD + h] = rsum[it * 2 + half];
            }
    }
    float* pn = g_pn + (size_t)sy * NTOK * 256;
#pragma unroll
    for (int it = 0; it < 2; it++)
#pragma unroll
        for (int n8 = 0; n8 < 4; n8++) {
            int r0 = i0 + it * 16 + (lane >> 2);
            int c = 32 * h + n8 * 8 + 2 * (lane & 3);
            *(float2*)(pn + (size_t)r0 * 256 + c) =
                make_float2(O[it][n8][0] * INV_PSCALE, O[it][n8][1] * INV_PSCALE);
            *(float2*)(pn + (size_t)(r0 + 8) * 256 + c) =
                make_float2(O[it][n8][2] * INV_PSCALE, O[it][n8][3] * INV_PSCALE);
        }

    /* ---- last CTA of this i-tile combines the NSPL partials (L2-hot) ---- */
    __syncthreads();
    __threadfence();
    if (t == 0) s_tick = atomicAdd(&g_tick[blockIdx.x], 1);
    __syncthreads();
    if (s_tick == NSPL - 1) {
        __threadfence();
#pragma unroll
        for (int k = 0; k < 8; k++) {
            int idx = t + k * 256;              /* 2048: 32 rows x 64 float4 */
            int row = i0 + (idx >> 6);
            int c0 = (idx & 63) * 4;
            float4 n = *(const float4*)(g_pn + (size_t)row * 256 + c0);
            float den = g_pd[row * NHEAD + (c0 >> 5)];
#pragma unroll
            for (int s = 1; s < NSPL; s++) {
                float4 n2 = *(const float4*)(g_pn + (size_t)s * NTOK * 256 + (size_t)row * 256 + c0);
                n.x += n2.x; n.y += n2.y; n.z += n2.z; n.w += n2.w;
                den += g_pd[s * NTOK * NHEAD + row * NHEAD + (c0 >> 5)];
            }
            float inv = 1.0f / den;
            __half h0, l0, h1, l1, h2, l2, h3, l3;
            hiloh(n.x * inv, h0, l0); hiloh(n.y * inv, h1, l1);
            hiloh(n.z * inv, h2, l2); hiloh(n.w * inv, h3, l3);
            __half* d = g_Xhl + (size_t)row * 256 + c0;
            *(ull*)d        = (ull)packh(h0, h1) | ((ull)packh(h2, h3) << 32);
            *(ull*)(d + NX) = (ull)packh(l0, l1) | ((ull)packh(l2, l3) << 32);
        }
    }
}

/* ================================================================= */
extern "C" void kernel_launch(void* const* d_in, const int* in_sizes, int n_in,
                              void* d_out, int out_size)
{
    const float* x    = (const float*)d_in[0];
    const float* pi   = (const float*)d_in[1];
    const float* tau  = (const float*)d_in[2];
    const float* adjs = (const float*)d_in[3];
    const float* Wq   = (const float*)d_in[4];
    const float* Wk   = (const float*)d_in[5];
    const float* Wv   = (const float*)d_in[6];
    const float* Wo   = (const float*)d_in[7];
    float* out = (float*)d_out;

    cudaFuncSetAttribute(attn_mma, cudaFuncAttributeMaxDynamicSharedMemorySize, SMEM_BYTES);
    cudaFuncSetAttribute(hgemm_qkv, cudaFuncAttributeMaxDynamicSharedMemorySize, HSMEM);
    cudaFuncSetAttribute(hgemm_out, cudaFuncAttributeMaxDynamicSharedMemorySize, HSMEM);

    conv_inputs<<<768, 256>>>(x, Wq, Wk, Wv, Wo);
    hgemm_qkv<<<dim3(12, 32), 256, HSMEM>>>();
    attn_mma<<<dim3(NTILE, NSPL), 256, SMEM_BYTES>>>(pi, tau, adjs);
    hgemm_out<<<dim3(4, 32), 256, HSMEM>>>(out);
}